// round 16
// baseline (speedup 1.0000x reference)
#include <cuda_runtime.h>
#include <cuda_fp16.h>
#include <cstdint>

#define Hdim 256
#define Bdim 2048
#define Tdim 512
#define Vdim 64
#define NB   16          // batches per CTA -> 128 CTAs
#define NTH  512         // 16 warps: pair p = wid&7, K-half kh = wid>>3
#define PSTR 266         // P row stride in floats
#define ESTR 68          // embT row stride in floats

// ---- shared memory layout (bytes) ----
// Fragment slots: slot[c][lane] = uint4, c = chunk 0..15 (h cols [16c,16c+16))
#define SM_P    0                      // P[64][PSTR] f32 = 68096
#define SM_F0   68096                  // h frag buf0: 16*512 = 8192
#define SM_F1   76288                  // h frag buf1: 8192
#define SM_TOK  84480                  // tokens [512][16] int = 32768 (end 117248)
#define SM_MBAR 117248                 // mbarrier (pad 128)
#define SM_SCR  117376                 // fp32 partial exchange: 32 slots x 512B = 16384
#define SM_EMBT 133760                 // transient embT f32 [256][ESTR] = 69632
#define SMEM_TOTAL (133760 + 69632)    // 203392

// ---------------------------------------------------------------------------
__device__ __forceinline__ uint32_t smem_u32(const void* p) {
    uint32_t a;
    asm("{ .reg .u64 t; cvta.to.shared.u64 t, %1; cvt.u32.u64 %0, t; }"
        : "=r"(a) : "l"(p));
    return a;
}
// sigmoid via single-MUFU tanh: s = 0.5*tanh(0.5x) + 0.5
__device__ __forceinline__ float sigmoid_t(float x) {
    float t;
    asm("tanh.approx.f32 %0, %1;" : "=f"(t) : "f"(0.5f * x));
    return fmaf(0.5f, t, 0.5f);
}
__device__ __forceinline__ void ffma2(unsigned long long& d,
                                      unsigned long long a, unsigned long long b) {
    asm("fma.rn.f32x2 %0, %1, %2, %0;" : "+l"(d) : "l"(a), "l"(b));
}
__device__ __forceinline__ unsigned long long pack2(float lo, float hi) {
    unsigned long long r;
    asm("mov.b64 %0, {%1, %2};" : "=l"(r) : "f"(lo), "f"(hi));
    return r;
}
__device__ __forceinline__ void mma16816(float* d, const uint32_t* a,
                                         uint32_t b0, uint32_t b1) {
    asm volatile(
        "mma.sync.aligned.m16n8k16.row.col.f32.f16.f16.f32 "
        "{%0,%1,%2,%3}, {%4,%5,%6,%7}, {%8,%9}, {%0,%1,%2,%3};"
        : "+f"(d[0]), "+f"(d[1]), "+f"(d[2]), "+f"(d[3])
        : "r"(a[0]), "r"(a[1]), "r"(a[2]), "r"(a[3]), "r"(b0), "r"(b1));
}
__device__ __forceinline__ void lds128(uint32_t* a, uint32_t addr) {
    asm volatile("ld.shared.v4.b32 {%0,%1,%2,%3}, [%4];"
                 : "=r"(a[0]), "=r"(a[1]), "=r"(a[2]), "=r"(a[3]) : "r"(addr));
}
__device__ __forceinline__ void lds128f(float* a, uint32_t addr) {
    asm volatile("ld.shared.v4.b32 {%0,%1,%2,%3}, [%4];"
                 : "=f"(a[0]), "=f"(a[1]), "=f"(a[2]), "=f"(a[3]) : "r"(addr));
}
__device__ __forceinline__ void sts128(uint32_t addr, uint32_t v0, uint32_t v1,
                                       uint32_t v2, uint32_t v3) {
    asm volatile("st.shared.v4.b32 [%0], {%1,%2,%3,%4};"
                 :: "r"(addr), "r"(v0), "r"(v1), "r"(v2), "r"(v3) : "memory");
}
__device__ __forceinline__ void sts128f(uint32_t addr, float v0, float v1,
                                        float v2, float v3) {
    asm volatile("st.shared.v4.b32 [%0], {%1,%2,%3,%4};"
                 :: "r"(addr), "f"(v0), "f"(v1), "f"(v2), "f"(v3) : "memory");
}
#define MBAR_INIT(mb, c) asm volatile("mbarrier.init.shared.b64 [%0], %1;" \
                                      :: "r"(mb), "r"(c) : "memory")
#define MBAR_ARRIVE(mb)  asm volatile("mbarrier.arrive.shared.b64 _, [%0];" \
                                      :: "r"(mb) : "memory")
__device__ __forceinline__ void mbar_wait(uint32_t mb, uint32_t parity) {
    asm volatile(
        "{ .reg .pred P;\n\t"
        "W_%=:\n\t"
        "mbarrier.try_wait.parity.acquire.cta.shared::cta.b64 P, [%0], %1, 0x989680;\n\t"
        "@P bra.uni D_%=;\n\t"
        "bra.uni W_%=;\n\t"
        "D_%=: }"
        :: "r"(mb), "r"(parity) : "memory");
}
__device__ __forceinline__ void bar_pair(int id) {
    asm volatile("bar.sync %0, 64;" :: "r"(id) : "memory");
}

// ---------------------------------------------------------------------------
// Persistent RNN: balanced K-split pairs + fragment-slot h exchange.
// Pair p = warps (p, p+8) owns outputs [32p, 32p+32) (4 n8 tiles). Warp
// (p,kh) MMAs K-half kh only (8 fragment LDS.128 instead of 16), sends its
// partials for the partner's 2 tiles as raw fp32 (2 constant-address
// STS.128), pair-bar, reads partner partials (2 LDS.128, 8 FADD), then
// reduces ITS tiles = outputs [32p+16kh, +16) = fragment chunk c = 2p+kh:
// sigmoid + ONE STS.128 publishes the chunk's A-fragment for next step.
// Main recurrence: proven single CTA mbarrier (all arrive once per step).
// ---------------------------------------------------------------------------
__global__ __launch_bounds__(NTH, 1)
void k_rnn(const int* __restrict__ tokens,
           const float* __restrict__ h0,
           const float* __restrict__ emb,
           const float* __restrict__ W,
           const float* __restrict__ bias,
           float* __restrict__ out) {
    extern __shared__ char smem[];
    const uint32_t sbase = smem_u32(smem);
    float* Psm  = (float*)(smem + SM_P);
    int*   toks = (int*)(smem + SM_TOK);
    const uint32_t mbar = sbase + SM_MBAR;

    const int tid  = threadIdx.x;
    const int wid  = tid >> 5;
    const int lane = tid & 31;
    const int g    = lane >> 2;     // 0..7
    const int r    = lane & 3;      // 0..3
    const int pair = wid & 7;       // 0..7
    const int kh   = wid >> 3;      // K-half 0/1
    const int bbase = blockIdx.x * NB;

    // ============== Prologue ==============
    {
        float* embT = (float*)(smem + SM_EMBT);
        for (int idx = tid; idx < Vdim * Hdim; idx += NTH) {
            int v = idx >> 8, k = idx & 255;
            embT[(size_t)k * ESTR + v] = emb[(size_t)v * Hdim + k];
        }
    }
    __syncthreads();
    {   // P[v][o] = bias[o] + emb[v,:]·Wx[o,:]; thread: o = tid&255, 2 v-groups
        const float* embT = (const float*)(smem + SM_EMBT);
        const int o = tid & 255;
        const int vg0 = (tid >> 8) * 2;
        const float bo = bias[o];
        const float4* wrow = (const float4*)(W + (size_t)o * (2 * Hdim));
        for (int vg = vg0; vg < vg0 + 2; ++vg) {
            unsigned long long acc[8];
#pragma unroll
            for (int i = 0; i < 8; ++i) acc[i] = pack2(0.f, 0.f);
            for (int k4 = 0; k4 < Hdim / 4; ++k4) {
                float4 wv = wrow[k4];
#pragma unroll
                for (int kk = 0; kk < 4; ++kk) {
                    int k = k4 * 4 + kk;
                    float w = (kk == 0) ? wv.x : (kk == 1) ? wv.y : (kk == 2) ? wv.z : wv.w;
                    unsigned long long wpair = pack2(w, w);
                    const ulonglong2* ep =
                        (const ulonglong2*)(embT + (size_t)k * ESTR + vg * 16);
                    ulonglong2 e0 = ep[0], e1 = ep[1], e2 = ep[2], e3 = ep[3];
                    ffma2(acc[0], wpair, e0.x); ffma2(acc[1], wpair, e0.y);
                    ffma2(acc[2], wpair, e1.x); ffma2(acc[3], wpair, e1.y);
                    ffma2(acc[4], wpair, e2.x); ffma2(acc[5], wpair, e2.y);
                    ffma2(acc[6], wpair, e3.x); ffma2(acc[7], wpair, e3.y);
                }
            }
#pragma unroll
            for (int i = 0; i < 8; ++i) {
                float lo = __uint_as_float((uint32_t)(acc[i] & 0xffffffffu));
                float hi = __uint_as_float((uint32_t)(acc[i] >> 32));
                int v0 = vg * 16 + 2 * i;
                Psm[(size_t)v0 * PSTR + o]       = bo + lo;
                Psm[(size_t)(v0 + 1) * PSTR + o] = bo + hi;
            }
        }
    }
    // B fragments: 4 n8 tiles (outputs [32p,32p+32)) over K-half kh (8 chunks)
    uint32_t breg[4][8][2];
#pragma unroll
    for (int nt = 0; nt < 4; ++nt) {
        int n = pair * 32 + nt * 8 + g;
        const float* wr = W + (size_t)n * (2 * Hdim) + Hdim;
#pragma unroll
        for (int c = 0; c < 8; ++c) {
            int k0 = (kh * 8 + c) * 16 + 2 * r;
            float2 lo = *(const float2*)&wr[k0];
            float2 hi = *(const float2*)&wr[k0 + 8];
            __half2 hlo = __floats2half2_rn(lo.x, lo.y);
            __half2 hhi = __floats2half2_rn(hi.x, hi.y);
            breg[nt][c][0] = *(uint32_t*)&hlo;
            breg[nt][c][1] = *(uint32_t*)&hhi;
        }
    }
    for (int idx = tid; idx < NB * Tdim; idx += NTH) {
        int b = idx >> 9, t = idx & 511;
        toks[t * NB + b] = tokens[(size_t)(bbase + b) * Tdim + t];
    }
    // h(0) in fragment layout: warp wid packs slot c = wid (16 slots, 16 warps)
    {
        int c = wid;
        int k0 = 16 * c + 2 * r;
        const float* h0b = h0 + (size_t)bbase * Hdim;
        __half2 q0 = __floats2half2_rn(h0b[(size_t)g * Hdim + k0],
                                       h0b[(size_t)g * Hdim + k0 + 1]);
        __half2 q1 = __floats2half2_rn(h0b[(size_t)(g + 8) * Hdim + k0],
                                       h0b[(size_t)(g + 8) * Hdim + k0 + 1]);
        __half2 q2 = __floats2half2_rn(h0b[(size_t)g * Hdim + k0 + 8],
                                       h0b[(size_t)g * Hdim + k0 + 9]);
        __half2 q3 = __floats2half2_rn(h0b[(size_t)(g + 8) * Hdim + k0 + 8],
                                       h0b[(size_t)(g + 8) * Hdim + k0 + 9]);
        sts128(sbase + SM_F0 + (uint32_t)(c * 512 + lane * 16),
               *(uint32_t*)&q0, *(uint32_t*)&q1, *(uint32_t*)&q2, *(uint32_t*)&q3);
    }
    if (tid == 0) MBAR_INIT(mbar, NTH);
    __syncthreads();
    MBAR_ARRIVE(mbar);       // phase 0: h(0) published

    // addressing
    const uint32_t fr_lane  = (uint32_t)(lane * 16);
    const int c_own  = 2 * pair + kh;                     // chunk this warp reduces
    const uint32_t slot_own = (uint32_t)(c_own * 512) + fr_lane;
    const uint32_t ldm_off  = (uint32_t)(kh * 8 * 512) + fr_lane;
    const int oR0 = pair * 32 + kh * 16 + 2 * r;          // reduce tile 0 cols
    const int oR1 = oR0 + 8;                              // reduce tile 1 cols
    const int st0 = 2 * (1 - kh);                         // local send-tile index
    // exchange: slot key = (pair, dest_kh, half); 512B each, lane*16 inside
    const uint32_t scr_send = sbase + SM_SCR
        + (uint32_t)(((pair * 2 + (1 - kh)) * 2) * 512) + fr_lane;
    const uint32_t scr_recv = sbase + SM_SCR
        + (uint32_t)(((pair * 2 + kh) * 2) * 512) + fr_lane;
    float* const outcta = out + (size_t)bbase * Hdim;

    // ============== Recurrent loop ==============
    for (int t = 0; t < Tdim; ++t) {
        // P/token prefetch for REDUCE tiles (stable regions, pre-wait)
        const int tk0 = toks[t * NB + g];
        const int tk1 = toks[t * NB + g + 8];
        float2 pA0 = *(const float2*)&Psm[(size_t)tk0 * PSTR + oR0];
        float2 pA1 = *(const float2*)&Psm[(size_t)tk1 * PSTR + oR0];
        float2 pB0 = *(const float2*)&Psm[(size_t)tk0 * PSTR + oR1];
        float2 pB1 = *(const float2*)&Psm[(size_t)tk1 * PSTR + oR1];

        float d[4][4];
#pragma unroll
        for (int nt = 0; nt < 4; ++nt)
#pragma unroll
            for (int j = 0; j < 4; ++j) d[nt][j] = 0.f;
        const int rt0 = 2 * kh, rt1 = 2 * kh + 1;
        d[rt0][0] = pA0.x; d[rt0][1] = pA0.y;
        d[rt0][2] = pA1.x; d[rt0][3] = pA1.y;
        d[rt1][0] = pB0.x; d[rt1][1] = pB0.y;
        d[rt1][2] = pB1.x; d[rt1][3] = pB1.y;

        mbar_wait(mbar, (uint32_t)(t & 1));
        const uint32_t abuf = sbase + ((t & 1) ? SM_F1 : SM_F0) + ldm_off;

        // own K-half: 8 fragment LDS.128, 4 independent HMMA chains
#pragma unroll
        for (int c = 0; c < 8; ++c) {
            uint32_t a[4];
            lds128(a, abuf + (uint32_t)c * 512);
            mma16816(d[0], a, breg[0][c][0], breg[0][c][1]);
            mma16816(d[1], a, breg[1][c][0], breg[1][c][1]);
            mma16816(d[2], a, breg[2][c][0], breg[2][c][1]);
            mma16816(d[3], a, breg[3][c][0], breg[3][c][1]);
        }

        // send partner's 2 tiles as raw fp32 (constant addresses, zero ALU)
        sts128f(scr_send,       d[st0][0],     d[st0][1],     d[st0][2],     d[st0][3]);
        sts128f(scr_send + 512, d[st0 + 1][0], d[st0 + 1][1], d[st0 + 1][2], d[st0 + 1][3]);
        bar_pair(pair + 1);
        float f0[4], f1[4];
        lds128f(f0, scr_recv);
        lds128f(f1, scr_recv + 512);

        // reduce own tiles, sigmoid, publish fragment slot (ONE STS.128)
        float s[2][4];
        s[0][0] = sigmoid_t(d[rt0][0] + f0[0]);
        s[0][1] = sigmoid_t(d[rt0][1] + f0[1]);
        s[0][2] = sigmoid_t(d[rt0][2] + f0[2]);
        s[0][3] = sigmoid_t(d[rt0][3] + f0[3]);
        s[1][0] = sigmoid_t(d[rt1][0] + f1[0]);
        s[1][1] = sigmoid_t(d[rt1][1] + f1[1]);
        s[1][2] = sigmoid_t(d[rt1][2] + f1[2]);
        s[1][3] = sigmoid_t(d[rt1][3] + f1[3]);
        {
            __half2 q0 = __floats2half2_rn(s[0][0], s[0][1]);
            __half2 q1 = __floats2half2_rn(s[0][2], s[0][3]);
            __half2 q2 = __floats2half2_rn(s[1][0], s[1][1]);
            __half2 q3 = __floats2half2_rn(s[1][2], s[1][3]);
            const uint32_t fnext = sbase + ((t & 1) ? SM_F0 : SM_F1) + slot_own;
            sts128(fnext, *(uint32_t*)&q0, *(uint32_t*)&q1,
                   *(uint32_t*)&q2, *(uint32_t*)&q3);
        }
        MBAR_ARRIVE(mbar);

        // output drain in the post-arrive shadow
        float* outp = outcta + (size_t)t * (Bdim * Hdim);
        *(float2*)&outp[(size_t)g * Hdim + oR0]       = make_float2(s[0][0], s[0][1]);
        *(float2*)&outp[(size_t)(g + 8) * Hdim + oR0] = make_float2(s[0][2], s[0][3]);
        *(float2*)&outp[(size_t)g * Hdim + oR1]       = make_float2(s[1][0], s[1][1]);
        *(float2*)&outp[(size_t)(g + 8) * Hdim + oR1] = make_float2(s[1][2], s[1][3]);
    }
}

// ---------------------------------------------------------------------------
// Harness entry.
// Inputs: tokens(i32 2048x512), h0(f32 2048x256), emb(f32 64x256),
//         W(f32 256x512), b(f32 256).  Output: f32 (512,2048,256)
// ---------------------------------------------------------------------------
extern "C" void kernel_launch(void* const* d_in, const int* in_sizes, int n_in,
                              void* d_out, int out_size) {
    const int*   tokens = (const int*)d_in[0];
    const float* h0     = (const float*)d_in[1];
    const float* emb    = (const float*)d_in[2];
    const float* W      = (const float*)d_in[3];
    const float* bias   = (const float*)d_in[4];
    float*       out    = (float*)d_out;
    (void)in_sizes; (void)n_in; (void)out_size;

    cudaFuncSetAttribute(k_rnn, cudaFuncAttributeMaxDynamicSharedMemorySize, SMEM_TOTAL);
    k_rnn<<<Bdim / NB, NTH, SMEM_TOTAL>>>(tokens, h0, emb, W, bias, out);
}

// round 17
// speedup vs baseline: 1.1568x; 1.1568x over previous
#include <cuda_runtime.h>
#include <cuda_fp16.h>
#include <cstdint>

#define Hdim 256
#define Bdim 2048
#define Tdim 512
#define Vdim 64
#define NB   16          // batches per CTA -> 128 CTAs
#define NTH  512         // 16 warps: pair p = wid&7, K-half kh = wid>>3
#define PSTR 266         // P row stride in floats
#define ESTR 68          // embT row stride in floats

// ---- shared memory layout (bytes) ----
// Fragment slots: slot[c][lane] = uint4, c = chunk 0..15 (h cols [16c,16c+16))
#define SM_P    0                      // P[64][PSTR] f32 = 68096
#define SM_F0   68096                  // h frag buf0: 16*512 = 8192
#define SM_F1   76288                  // h frag buf1: 8192
#define SM_TOK  84480                  // tokens [512][16] int = 32768 (end 117248)
#define SM_MBAR 117248                 // mbarrier (pad 128)
#define SM_SCR  117376                 // fp32 partial exchange: 32 slots x 512B = 16384
#define SM_EMBT 133760                 // transient embT f32 [256][ESTR] = 69632
#define SMEM_TOTAL (133760 + 69632)    // 203392

// ---------------------------------------------------------------------------
__device__ __forceinline__ uint32_t smem_u32(const void* p) {
    uint32_t a;
    asm("{ .reg .u64 t; cvta.to.shared.u64 t, %1; cvt.u32.u64 %0, t; }"
        : "=r"(a) : "l"(p));
    return a;
}
// sigmoid via single-MUFU tanh: s = 0.5*tanh(0.5x) + 0.5
__device__ __forceinline__ float sigmoid_t(float x) {
    float t;
    asm("tanh.approx.f32 %0, %1;" : "=f"(t) : "f"(0.5f * x));
    return fmaf(0.5f, t, 0.5f);
}
__device__ __forceinline__ void ffma2(unsigned long long& d,
                                      unsigned long long a, unsigned long long b) {
    asm("fma.rn.f32x2 %0, %1, %2, %0;" : "+l"(d) : "l"(a), "l"(b));
}
__device__ __forceinline__ unsigned long long pack2(float lo, float hi) {
    unsigned long long r;
    asm("mov.b64 %0, {%1, %2};" : "=l"(r) : "f"(lo), "f"(hi));
    return r;
}
__device__ __forceinline__ void mma16816(float* d, const uint32_t* a,
                                         uint32_t b0, uint32_t b1) {
    asm volatile(
        "mma.sync.aligned.m16n8k16.row.col.f32.f16.f16.f32 "
        "{%0,%1,%2,%3}, {%4,%5,%6,%7}, {%8,%9}, {%0,%1,%2,%3};"
        : "+f"(d[0]), "+f"(d[1]), "+f"(d[2]), "+f"(d[3])
        : "r"(a[0]), "r"(a[1]), "r"(a[2]), "r"(a[3]), "r"(b0), "r"(b1));
}
__device__ __forceinline__ void lds128(uint32_t* a, uint32_t addr) {
    asm volatile("ld.shared.v4.b32 {%0,%1,%2,%3}, [%4];"
                 : "=r"(a[0]), "=r"(a[1]), "=r"(a[2]), "=r"(a[3]) : "r"(addr));
}
__device__ __forceinline__ void lds128f(float* a, uint32_t addr) {
    asm volatile("ld.shared.v4.b32 {%0,%1,%2,%3}, [%4];"
                 : "=f"(a[0]), "=f"(a[1]), "=f"(a[2]), "=f"(a[3]) : "r"(addr));
}
__device__ __forceinline__ void sts128(uint32_t addr, uint32_t v0, uint32_t v1,
                                       uint32_t v2, uint32_t v3) {
    asm volatile("st.shared.v4.b32 [%0], {%1,%2,%3,%4};"
                 :: "r"(addr), "r"(v0), "r"(v1), "r"(v2), "r"(v3) : "memory");
}
__device__ __forceinline__ void sts128f(uint32_t addr, float v0, float v1,
                                        float v2, float v3) {
    asm volatile("st.shared.v4.b32 [%0], {%1,%2,%3,%4};"
                 :: "r"(addr), "f"(v0), "f"(v1), "f"(v2), "f"(v3) : "memory");
}
#define MBAR_INIT(mb, c) asm volatile("mbarrier.init.shared.b64 [%0], %1;" \
                                      :: "r"(mb), "r"(c) : "memory")
#define MBAR_ARRIVE(mb)  asm volatile("mbarrier.arrive.shared.b64 _, [%0];" \
                                      :: "r"(mb) : "memory")
__device__ __forceinline__ void mbar_wait(uint32_t mb, uint32_t parity) {
    asm volatile(
        "{ .reg .pred P;\n\t"
        "W_%=:\n\t"
        "mbarrier.try_wait.parity.acquire.cta.shared::cta.b64 P, [%0], %1, 0x989680;\n\t"
        "@P bra.uni D_%=;\n\t"
        "bra.uni W_%=;\n\t"
        "D_%=: }"
        :: "r"(mb), "r"(parity) : "memory");
}
__device__ __forceinline__ void bar_pair(int id) {
    asm volatile("bar.sync %0, 64;" :: "r"(id) : "memory");
}

// ---------------------------------------------------------------------------
// Persistent RNN: balanced K-split pairs + fragment-slot h exchange.
// Pair p = warps (p, p+8) owns outputs [32p, 32p+32). Warp (p,kh) MMAs
// K-half kh only (8 fragment LDS.128/step). Register arrays are ALL
// constant-indexed: breg[0..1] / dR = this warp's REDUCE tiles (outputs
// [32p+16kh, +16)); breg[2..3] / dS = the partner's tiles (sent as raw fp32
// via 2 constant-address STS.128). Leaf bar.sync(pair+1,64) orders the
// exchange; reduce + sigmoid + ONE STS.128 publishes fragment chunk
// c = 2p+kh. Main recurrence: proven single CTA mbarrier.
// ---------------------------------------------------------------------------
__global__ __launch_bounds__(NTH, 1)
void k_rnn(const int* __restrict__ tokens,
           const float* __restrict__ h0,
           const float* __restrict__ emb,
           const float* __restrict__ W,
           const float* __restrict__ bias,
           float* __restrict__ out) {
    extern __shared__ char smem[];
    const uint32_t sbase = smem_u32(smem);
    float* Psm  = (float*)(smem + SM_P);
    int*   toks = (int*)(smem + SM_TOK);
    const uint32_t mbar = sbase + SM_MBAR;

    const int tid  = threadIdx.x;
    const int wid  = tid >> 5;
    const int lane = tid & 31;
    const int g    = lane >> 2;     // 0..7
    const int r    = lane & 3;      // 0..3
    const int pair = wid & 7;       // 0..7
    const int kh   = wid >> 3;      // K-half 0/1
    const int bbase = blockIdx.x * NB;

    // ============== Prologue ==============
    {
        float* embT = (float*)(smem + SM_EMBT);
        for (int idx = tid; idx < Vdim * Hdim; idx += NTH) {
            int v = idx >> 8, k = idx & 255;
            embT[(size_t)k * ESTR + v] = emb[(size_t)v * Hdim + k];
        }
    }
    __syncthreads();
    {   // P[v][o] = bias[o] + emb[v,:]·Wx[o,:]; thread: o = tid&255, 2 v-groups
        const float* embT = (const float*)(smem + SM_EMBT);
        const int o = tid & 255;
        const int vg0 = (tid >> 8) * 2;
        const float bo = bias[o];
        const float4* wrow = (const float4*)(W + (size_t)o * (2 * Hdim));
        for (int vg = vg0; vg < vg0 + 2; ++vg) {
            unsigned long long acc[8];
#pragma unroll
            for (int i = 0; i < 8; ++i) acc[i] = pack2(0.f, 0.f);
            for (int k4 = 0; k4 < Hdim / 4; ++k4) {
                float4 wv = wrow[k4];
#pragma unroll
                for (int kk = 0; kk < 4; ++kk) {
                    int k = k4 * 4 + kk;
                    float w = (kk == 0) ? wv.x : (kk == 1) ? wv.y : (kk == 2) ? wv.z : wv.w;
                    unsigned long long wpair = pack2(w, w);
                    const ulonglong2* ep =
                        (const ulonglong2*)(embT + (size_t)k * ESTR + vg * 16);
                    ulonglong2 e0 = ep[0], e1 = ep[1], e2 = ep[2], e3 = ep[3];
                    ffma2(acc[0], wpair, e0.x); ffma2(acc[1], wpair, e0.y);
                    ffma2(acc[2], wpair, e1.x); ffma2(acc[3], wpair, e1.y);
                    ffma2(acc[4], wpair, e2.x); ffma2(acc[5], wpair, e2.y);
                    ffma2(acc[6], wpair, e3.x); ffma2(acc[7], wpair, e3.y);
                }
            }
#pragma unroll
            for (int i = 0; i < 8; ++i) {
                float lo = __uint_as_float((uint32_t)(acc[i] & 0xffffffffu));
                float hi = __uint_as_float((uint32_t)(acc[i] >> 32));
                int v0 = vg * 16 + 2 * i;
                Psm[(size_t)v0 * PSTR + o]       = bo + lo;
                Psm[(size_t)(v0 + 1) * PSTR + o] = bo + hi;
            }
        }
    }
    // B fragments over K-half kh. Tile remap (kh folded in at load time):
    //   breg[0],breg[1]: REDUCE tiles -> outputs 32p + 16*kh     + {0,8} + g
    //   breg[2],breg[3]: SEND tiles   -> outputs 32p + 16*(1-kh) + {0,8} + g
    uint32_t breg[4][8][2];
#pragma unroll
    for (int nt = 0; nt < 4; ++nt) {
        const int half_sel = (nt < 2) ? kh : (1 - kh);
        int n = pair * 32 + half_sel * 16 + (nt & 1) * 8 + g;
        const float* wr = W + (size_t)n * (2 * Hdim) + Hdim;
#pragma unroll
        for (int c = 0; c < 8; ++c) {
            int k0 = (kh * 8 + c) * 16 + 2 * r;
            float2 lo = *(const float2*)&wr[k0];
            float2 hi = *(const float2*)&wr[k0 + 8];
            __half2 hlo = __floats2half2_rn(lo.x, lo.y);
            __half2 hhi = __floats2half2_rn(hi.x, hi.y);
            breg[nt][c][0] = *(uint32_t*)&hlo;
            breg[nt][c][1] = *(uint32_t*)&hhi;
        }
    }
    for (int idx = tid; idx < NB * Tdim; idx += NTH) {
        int b = idx >> 9, t = idx & 511;
        toks[t * NB + b] = tokens[(size_t)(bbase + b) * Tdim + t];
    }
    // h(0) in fragment layout: warp wid packs slot c = wid
    {
        int c = wid;
        int k0 = 16 * c + 2 * r;
        const float* h0b = h0 + (size_t)bbase * Hdim;
        __half2 q0 = __floats2half2_rn(h0b[(size_t)g * Hdim + k0],
                                       h0b[(size_t)g * Hdim + k0 + 1]);
        __half2 q1 = __floats2half2_rn(h0b[(size_t)(g + 8) * Hdim + k0],
                                       h0b[(size_t)(g + 8) * Hdim + k0 + 1]);
        __half2 q2 = __floats2half2_rn(h0b[(size_t)g * Hdim + k0 + 8],
                                       h0b[(size_t)g * Hdim + k0 + 9]);
        __half2 q3 = __floats2half2_rn(h0b[(size_t)(g + 8) * Hdim + k0 + 8],
                                       h0b[(size_t)(g + 8) * Hdim + k0 + 9]);
        sts128(sbase + SM_F0 + (uint32_t)(c * 512 + lane * 16),
               *(uint32_t*)&q0, *(uint32_t*)&q1, *(uint32_t*)&q2, *(uint32_t*)&q3);
    }
    if (tid == 0) MBAR_INIT(mbar, NTH);
    __syncthreads();
    MBAR_ARRIVE(mbar);       // phase 0: h(0) published

    // addressing (all scalars; no runtime register-array indexing below)
    const uint32_t fr_lane  = (uint32_t)(lane * 16);
    const int c_own  = 2 * pair + kh;                     // chunk this warp reduces
    const uint32_t slot_own = (uint32_t)(c_own * 512) + fr_lane;
    const uint32_t ldm_off  = (uint32_t)(kh * 8 * 512) + fr_lane;
    const int oR0 = pair * 32 + kh * 16 + 2 * r;          // reduce tile 0 cols
    const int oR1 = oR0 + 8;                              // reduce tile 1 cols
    const uint32_t scr_send = sbase + SM_SCR
        + (uint32_t)(((pair * 2 + (1 - kh)) * 2) * 512) + fr_lane;
    const uint32_t scr_recv = sbase + SM_SCR
        + (uint32_t)(((pair * 2 + kh) * 2) * 512) + fr_lane;
    float* const outcta = out + (size_t)bbase * Hdim;

    // ============== Recurrent loop ==============
    for (int t = 0; t < Tdim; ++t) {
        // P/token prefetch for REDUCE tiles (stable regions, pre-wait)
        const int tk0 = toks[t * NB + g];
        const int tk1 = toks[t * NB + g + 8];
        float2 pA0 = *(const float2*)&Psm[(size_t)tk0 * PSTR + oR0];
        float2 pA1 = *(const float2*)&Psm[(size_t)tk1 * PSTR + oR0];
        float2 pB0 = *(const float2*)&Psm[(size_t)tk0 * PSTR + oR1];
        float2 pB1 = *(const float2*)&Psm[(size_t)tk1 * PSTR + oR1];

        // constant-indexed accumulators
        float dR0[4], dR1[4], dS0[4], dS1[4];
        dR0[0] = pA0.x; dR0[1] = pA0.y; dR0[2] = pA1.x; dR0[3] = pA1.y;
        dR1[0] = pB0.x; dR1[1] = pB0.y; dR1[2] = pB1.x; dR1[3] = pB1.y;
#pragma unroll
        for (int j = 0; j < 4; ++j) { dS0[j] = 0.f; dS1[j] = 0.f; }

        mbar_wait(mbar, (uint32_t)(t & 1));
        const uint32_t abuf = sbase + ((t & 1) ? SM_F1 : SM_F0) + ldm_off;

        // own K-half: 8 fragment LDS.128, 4 independent HMMA chains
#pragma unroll
        for (int c = 0; c < 8; ++c) {
            uint32_t a[4];
            lds128(a, abuf + (uint32_t)c * 512);
            mma16816(dR0, a, breg[0][c][0], breg[0][c][1]);
            mma16816(dR1, a, breg[1][c][0], breg[1][c][1]);
            mma16816(dS0, a, breg[2][c][0], breg[2][c][1]);
            mma16816(dS1, a, breg[3][c][0], breg[3][c][1]);
        }

        // send partner's 2 tiles as raw fp32 (constant addrs, no index math)
        sts128f(scr_send,       dS0[0], dS0[1], dS0[2], dS0[3]);
        sts128f(scr_send + 512, dS1[0], dS1[1], dS1[2], dS1[3]);
        bar_pair(pair + 1);
        float f0[4], f1[4];
        lds128f(f0, scr_recv);
        lds128f(f1, scr_recv + 512);

        // reduce own tiles, sigmoid, publish fragment slot (ONE STS.128)
        float s0[4], s1[4];
        s0[0] = sigmoid_t(dR0[0] + f0[0]);
        s0[1] = sigmoid_t(dR0[1] + f0[1]);
        s0[2] = sigmoid_t(dR0[2] + f0[2]);
        s0[3] = sigmoid_t(dR0[3] + f0[3]);
        s1[0] = sigmoid_t(dR1[0] + f1[0]);
        s1[1] = sigmoid_t(dR1[1] + f1[1]);
        s1[2] = sigmoid_t(dR1[2] + f1[2]);
        s1[3] = sigmoid_t(dR1[3] + f1[3]);
        {
            __half2 q0 = __floats2half2_rn(s0[0], s0[1]);
            __half2 q1 = __floats2half2_rn(s0[2], s0[3]);
            __half2 q2 = __floats2half2_rn(s1[0], s1[1]);
            __half2 q3 = __floats2half2_rn(s1[2], s1[3]);
            const uint32_t fnext = sbase + ((t & 1) ? SM_F0 : SM_F1) + slot_own;
            sts128(fnext, *(uint32_t*)&q0, *(uint32_t*)&q1,
                   *(uint32_t*)&q2, *(uint32_t*)&q3);
        }
        MBAR_ARRIVE(mbar);

        // output drain in the post-arrive shadow
        float* outp = outcta + (size_t)t * (Bdim * Hdim);
        *(float2*)&outp[(size_t)g * Hdim + oR0]       = make_float2(s0[0], s0[1]);
        *(float2*)&outp[(size_t)(g + 8) * Hdim + oR0] = make_float2(s0[2], s0[3]);
        *(float2*)&outp[(size_t)g * Hdim + oR1]       = make_float2(s1[0], s1[1]);
        *(float2*)&outp[(size_t)(g + 8) * Hdim + oR1] = make_float2(s1[2], s1[3]);
    }
}

// ---------------------------------------------------------------------------
// Harness entry.
// Inputs: tokens(i32 2048x512), h0(f32 2048x256), emb(f32 64x256),
//         W(f32 256x512), b(f32 256).  Output: f32 (512,2048,256)
// ---------------------------------------------------------------------------
extern "C" void kernel_launch(void* const* d_in, const int* in_sizes, int n_in,
                              void* d_out, int out_size) {
    const int*   tokens = (const int*)d_in[0];
    const float* h0     = (const float*)d_in[1];
    const float* emb    = (const float*)d_in[2];
    const float* W      = (const float*)d_in[3];
    const float* bias   = (const float*)d_in[4];
    float*       out    = (float*)d_out;
    (void)in_sizes; (void)n_in; (void)out_size;

    cudaFuncSetAttribute(k_rnn, cudaFuncAttributeMaxDynamicSharedMemorySize, SMEM_TOTAL);
    k_rnn<<<Bdim / NB, NTH, SMEM_TOTAL>>>(tokens, h0, emb, W, bias, out);
}